// round 5
// baseline (speedup 1.0000x reference)
#include <cuda_runtime.h>
#include <cstddef>

#define FULLMASK 0xffffffffu

// Global scratch (static __device__ arrays - no allocation at runtime)
static __device__ float g_patch[16384 * 784];      // 51.4 MB patch-major grayscale
static __device__ float g_tok2[16384 * 49 * 16];   // 51.4 MB stage-1 output

// ---------------------------------------------------------------------------
// Kernel P: grayscale + patch scatter. x (B,3,28,28) -> g_patch [b][s][j]
// ---------------------------------------------------------------------------
__global__ void vitP(const float* __restrict__ x)
{
    int idx = blockIdx.x * 256 + threadIdx.x;
    if (idx >= 16384 * 784) return;
    int b = idx / 784;
    int p = idx - b * 784;
    const float* xb = x + (size_t)b * 2352;
    float g = 0.299f * xb[p] + 0.587f * xb[784 + p] + 0.114f * xb[1568 + p];
    int py = p / 28, px = p - py * 28;
    g_patch[(size_t)b * 784 + ((py >> 2) * 7 + (px >> 2)) * 16 + ((py & 3) << 2) + (px & 3)] = g;
}

// 16 FMAs of a float4-quad weight block against patch quads p0..p3
#define FMA16(acc0, acc1, W0, W1, W2, W3)                                   \
    acc0 = fmaf(p0.x, W0.x, acc0); acc1 = fmaf(p0.y, W0.y, acc1);           \
    acc0 = fmaf(p0.z, W0.z, acc0); acc1 = fmaf(p0.w, W0.w, acc1);           \
    acc0 = fmaf(p1.x, W1.x, acc0); acc1 = fmaf(p1.y, W1.y, acc1);           \
    acc0 = fmaf(p1.z, W1.z, acc0); acc1 = fmaf(p1.w, W1.w, acc1);           \
    acc0 = fmaf(p2.x, W2.x, acc0); acc1 = fmaf(p2.y, W2.y, acc1);           \
    acc0 = fmaf(p2.z, W2.z, acc0); acc1 = fmaf(p2.w, W2.w, acc1);           \
    acc0 = fmaf(p3.x, W3.x, acc0); acc1 = fmaf(p3.y, W3.y, acc1);           \
    acc0 = fmaf(p3.z, W3.z, acc0); acc1 = fmaf(p3.w, W3.w, acc1);

// ---------------------------------------------------------------------------
// Kernel A (merged stage 1): patches -> Q,K -> S gram -> V -> softmax -> tok2
// Warp = 2 half-warps = 2 elements, both halves iterate the SAME s:
// weight LDS.128 reads 16 lanes x 16B = 256B, broadcast across halves -> 2 wf.
// Weight layout [w][s][i/4][d][4]. 448 threads = 14 warps.
// SMEM: 3*12544 + 3*784 = 39984 floats = 159936 B.
// ---------------------------------------------------------------------------
__global__ void __launch_bounds__(448, 1) vitA(
    const float* __restrict__ pe,
    const float* __restrict__ WQ1,
    const float* __restrict__ WK1,
    const float* __restrict__ WV1)
{
    extern __shared__ float sm[];
    float* sW = sm;          // 3 * 12544
    float* sB = sm + 37632;  // 3 * 784

    const int tid = threadIdx.x;
    {
        const float* Wg[3] = {WQ1, WK1, WV1};
        for (int w = 0; w < 3; ++w) {
            const float* G = Wg[w];
            float* dst = sW + w * 12544;
            for (int idx = tid; idx < 12544; idx += 448) {
                int s = idx >> 8, r = idx & 255, i = r >> 4, o = r & 15;
                dst[s * 256 + (i >> 2) * 64 + o * 4 + (i & 3)] = G[(s * 16 + o) * 32 + i];
            }
            float* db = sB + w * 784;
            for (int idx = tid; idx < 784; idx += 448) {
                int s = idx >> 4, o = idx & 15;
                const float* gw = G + (s * 16 + o) * 32 + 16;
                const float* pp = pe + s * 16;
                float acc = 0.f;
#pragma unroll
                for (int j = 0; j < 16; ++j) acc = fmaf(pp[j], gw[j], acc);
                db[idx] = acc;
            }
        }
    }
    __syncthreads();

    const int warpId = tid >> 5;
    const int lane = tid & 31;
    const int hh = lane >> 4;
    const int l16 = lane & 15;
    const int nwarp = gridDim.x * 14;

    for (int pair = blockIdx.x * 14 + warpId; pair < 8192; pair += nwarp) {
        const int elem = pair * 2 + hh;
        const float* pb = g_patch + (size_t)elem * 784;

        float S[16];
#pragma unroll
        for (int e = 0; e < 16; ++e) S[e] = 0.f;

        // ---- pass 1: q,k -> gram ----
#pragma unroll 1
        for (int s = 0; s < 49; ++s) {
            const float4* pv = (const float4*)(pb + s * 16);
            float4 p0 = __ldg(pv + 0), p1 = __ldg(pv + 1);
            float4 p2 = __ldg(pv + 2), p3 = __ldg(pv + 3);

            const float4* wq4 = (const float4*)(sW + s * 256 + l16 * 4);
            float4 a0 = wq4[0], a1 = wq4[16], a2 = wq4[32], a3 = wq4[48];
            float q0 = sB[s * 16 + l16], q1 = 0.f;
            FMA16(q0, q1, a0, a1, a2, a3);

            const float4* wk4 = (const float4*)(sW + 12544 + s * 256 + l16 * 4);
            float4 b0 = wk4[0], b1 = wk4[16], b2 = wk4[32], b3 = wk4[48];
            float k0 = sB[784 + s * 16 + l16], k1 = 0.f;
            FMA16(k0, k1, b0, b1, b2, b3);

            float q = q0 + q1;
            float k = k0 + k1;
#pragma unroll
            for (int e = 0; e < 16; ++e) {
                float ke = __shfl_sync(FULLMASK, k, e, 16);
                S[e] = fmaf(q, ke, S[e]);
            }
        }
#pragma unroll
        for (int e = 0; e < 16; ++e) S[e] *= (1.f / 7.f);

        // ---- pass 2: v -> apply S -> softmax(16) -> tok2 ----
        float* ob = g_tok2 + (size_t)elem * 784;
#pragma unroll 1
        for (int s = 0; s < 49; ++s) {
            const float4* pv = (const float4*)(pb + s * 16);
            float4 p0 = __ldg(pv + 0), p1 = __ldg(pv + 1);
            float4 p2 = __ldg(pv + 2), p3 = __ldg(pv + 3);

            const float4* wv4 = (const float4*)(sW + 25088 + s * 256 + l16 * 4);
            float4 a0 = wv4[0], a1 = wv4[16], a2 = wv4[32], a3 = wv4[48];
            float v0 = sB[1568 + s * 16 + l16], v1 = 0.f;
            FMA16(v0, v1, a0, a1, a2, a3);
            float v = v0 + v1;

            float o = 0.f;
#pragma unroll
            for (int e = 0; e < 16; ++e) {
                float ve = __shfl_sync(FULLMASK, v, e, 16);
                o = fmaf(S[e], ve, o);
            }
            float m = o;
#pragma unroll
            for (int dd = 8; dd; dd >>= 1)
                m = fmaxf(m, __shfl_xor_sync(FULLMASK, m, dd, 16));
            float ex = __expf(o - m);
            float sum = ex;
#pragma unroll
            for (int dd = 8; dd; dd >>= 1)
                sum += __shfl_xor_sync(FULLMASK, sum, dd, 16);
            ob[s * 16 + l16] = __fdividef(ex, sum);
        }
    }
}

// ---------------------------------------------------------------------------
// Kernel B: tok2 -> QKV2 -> attn(8) -> softmax -> tok3 -> fc1 -> relu -> fc2
// Warp = 4 octets = 4 elements, all octets share the same s:
// weight LDS.128 = 8 lanes x 16B = 128B broadcast x4 -> 1 wavefront, /4 elems.
// 448 threads = 14 warps. SMEM: 3*6272 + 6272 + 160 + 32 + 14*1568
// = 47232 floats = 188928 B.
// ---------------------------------------------------------------------------
__global__ void __launch_bounds__(448, 1) vitB(
    const float* __restrict__ WQ2,
    const float* __restrict__ WK2,
    const float* __restrict__ WV2,
    const float* __restrict__ f1w,
    const float* __restrict__ f1b,
    const float* __restrict__ f2w,
    const float* __restrict__ f2b,
    float* __restrict__ out)
{
    extern __shared__ float sm[];
    float* sW2 = sm;            // 3 * 6272
    float* sF1 = sm + 18816;    // 6272
    float* sF2 = sm + 25088;    // 160
    float* sB1 = sm + 25248;    // 16
    float* sB2 = sm + 25264;    // 16
    float* sT3 = sm + 25280;    // 14 warps * 4 elems * 392

    const int tid = threadIdx.x;
    {
        const float* Wg[3] = {WQ2, WK2, WV2};
        for (int w = 0; w < 3; ++w) {
            const float* G = Wg[w];
            float* dst = sW2 + w * 6272;
            for (int idx = tid; idx < 6272; idx += 448) {
                int s = idx >> 7, r = idx & 127, i = r >> 3, d = r & 7;
                dst[s * 128 + (i >> 2) * 32 + d * 4 + (i & 3)] = G[(s * 8 + d) * 16 + i];
            }
        }
        for (int idx = tid; idx < 6272; idx += 448) {
            int k = idx >> 4, j = idx & 15;
            sF1[(k >> 2) * 64 + j * 4 + (k & 3)] = f1w[j * 392 + k];
        }
        for (int idx = tid; idx < 160; idx += 448) {
            int j = idx / 10, c = idx - j * 10;
            sF2[idx] = f2w[c * 16 + j];
        }
        if (tid < 16) sB1[tid] = f1b[tid];
        if (tid < 10) sB2[tid] = f2b[tid];
    }
    __syncthreads();

    const int warpId = tid >> 5;
    const int lane = tid & 31;
    const int oct = lane >> 3;   // 0..3 : element within group
    const int d8 = lane & 7;     // output dim
    float* t3w = sT3 + warpId * 1568;
    float* t3o = t3w + oct * 392;
    const int nwarp = gridDim.x * 14;

    for (int grp = blockIdx.x * 14 + warpId; grp < 4096; grp += nwarp) {
        const int elem = grp * 4 + oct;
        const float* tb = g_tok2 + (size_t)elem * 784;

        float S2[8];
#pragma unroll
        for (int e = 0; e < 8; ++e) S2[e] = 0.f;

        // ---- pass 1: q2,k2 -> gram (octet-local, full s range) ----
#pragma unroll 1
        for (int s = 0; s < 49; ++s) {
            const float4* pv = (const float4*)(tb + s * 16);
            float4 p0 = __ldg(pv + 0), p1 = __ldg(pv + 1);
            float4 p2 = __ldg(pv + 2), p3 = __ldg(pv + 3);

            const float4* wq4 = (const float4*)(sW2 + s * 128 + d8 * 4);
            float4 a0 = wq4[0], a1 = wq4[8], a2 = wq4[16], a3 = wq4[24];
            float q0 = 0.f, q1 = 0.f;
            FMA16(q0, q1, a0, a1, a2, a3);

            const float4* wk4 = (const float4*)(sW2 + 6272 + s * 128 + d8 * 4);
            float4 b0 = wk4[0], b1 = wk4[8], b2 = wk4[16], b3 = wk4[24];
            float k0 = 0.f, k1 = 0.f;
            FMA16(k0, k1, b0, b1, b2, b3);

            float q = q0 + q1;
            float k = k0 + k1;
#pragma unroll
            for (int e = 0; e < 8; ++e) {
                float ke = __shfl_sync(FULLMASK, k, e, 8);
                S2[e] = fmaf(q, ke, S2[e]);
            }
        }
#pragma unroll
        for (int e = 0; e < 8; ++e) S2[e] *= (1.f / 7.f);

        // ---- pass 2: v2 -> apply S2 -> softmax(8) -> t3 ----
#pragma unroll 1
        for (int s = 0; s < 49; ++s) {
            const float4* pv = (const float4*)(tb + s * 16);
            float4 p0 = __ldg(pv + 0), p1 = __ldg(pv + 1);
            float4 p2 = __ldg(pv + 2), p3 = __ldg(pv + 3);

            const float4* wv4 = (const float4*)(sW2 + 12544 + s * 128 + d8 * 4);
            float4 a0 = wv4[0], a1 = wv4[8], a2 = wv4[16], a3 = wv4[24];
            float v0 = 0.f, v1 = 0.f;
            FMA16(v0, v1, a0, a1, a2, a3);
            float v = v0 + v1;

            float o = 0.f;
#pragma unroll
            for (int e = 0; e < 8; ++e) {
                float ve = __shfl_sync(FULLMASK, v, e, 8);
                o = fmaf(S2[e], ve, o);
            }
            float m = o;
#pragma unroll
            for (int dd = 4; dd; dd >>= 1)
                m = fmaxf(m, __shfl_xor_sync(FULLMASK, m, dd, 8));
            float ex = __expf(o - m);
            float sum = ex;
#pragma unroll
            for (int dd = 4; dd; dd >>= 1)
                sum += __shfl_xor_sync(FULLMASK, sum, dd, 8);
            t3o[s * 8 + d8] = __fdividef(ex, sum);
        }
        __syncwarp();

        // ---- fc1: lane (oct,d8) computes h[d8], h[d8+8] of its element ----
        float h0 = 0.f, h1 = 0.f;
#pragma unroll 7
        for (int k4 = 0; k4 < 98; ++k4) {
            float4 tv = *(const float4*)(t3o + k4 * 4);
            float4 w0 = *(const float4*)(sF1 + k4 * 64 + d8 * 4);
            float4 w1 = *(const float4*)(sF1 + k4 * 64 + (d8 + 8) * 4);
            h0 = fmaf(tv.x, w0.x, h0); h1 = fmaf(tv.x, w1.x, h1);
            h0 = fmaf(tv.y, w0.y, h0); h1 = fmaf(tv.y, w1.y, h1);
            h0 = fmaf(tv.z, w0.z, h0); h1 = fmaf(tv.z, w1.z, h1);
            h0 = fmaf(tv.w, w0.w, h0); h1 = fmaf(tv.w, w1.w, h1);
        }
        h0 = fmaxf(h0 + sB1[d8], 0.f);
        h1 = fmaxf(h1 + sB1[d8 + 8], 0.f);

        // stash h into (now dead) t3 area for the fc2 transpose
        __syncwarp();
        float* hb = t3w;             // 64 floats: [oct][16]
        hb[oct * 16 + d8] = h0;
        hb[oct * 16 + d8 + 8] = h1;
        __syncwarp();

        // ---- fc2 + softmax over 10 (octet-local) ----
        const float* ho = hb + oct * 16;
        int c2 = (d8 < 2) ? (d8 + 8) : 8;  // clamp keeps reads in-bounds
        float lg1 = sB2[d8];
        float lg2 = sB2[c2];
#pragma unroll
        for (int j = 0; j < 16; ++j) {
            float hv = ho[j];
            lg1 = fmaf(hv, sF2[j * 10 + d8], lg1);
            lg2 = fmaf(hv, sF2[j * 10 + c2], lg2);
        }
        float lg2v = (d8 < 2) ? lg2 : -1e30f;
        float m = fmaxf(lg1, lg2v);
#pragma unroll
        for (int dd = 4; dd; dd >>= 1)
            m = fmaxf(m, __shfl_xor_sync(FULLMASK, m, dd, 8));
        float e1 = __expf(lg1 - m);
        float e2 = (d8 < 2) ? __expf(lg2 - m) : 0.f;
        float sum = e1 + e2;
#pragma unroll
        for (int dd = 4; dd; dd >>= 1)
            sum += __shfl_xor_sync(FULLMASK, sum, dd, 8);
        float inv = __fdividef(1.f, sum);
        out[elem * 10 + d8] = e1 * inv;
        if (d8 < 2) out[elem * 10 + 8 + d8] = e2 * inv;
        __syncwarp();  // protect hb/t3 before next iteration's pass 2
    }
}

extern "C" void kernel_launch(void* const* d_in, const int* in_sizes, int n_in,
                              void* d_out, int out_size)
{
    (void)in_sizes; (void)n_in; (void)out_size;
    const float* x   = (const float*)d_in[0];
    const float* pe  = (const float*)d_in[1];
    const float* WQ1 = (const float*)d_in[2];
    const float* WK1 = (const float*)d_in[3];
    const float* WV1 = (const float*)d_in[4];
    const float* WQ2 = (const float*)d_in[5];
    const float* WK2 = (const float*)d_in[6];
    const float* WV2 = (const float*)d_in[7];
    const float* f1w = (const float*)d_in[8];
    const float* f1b = (const float*)d_in[9];
    const float* f2w = (const float*)d_in[10];
    const float* f2b = (const float*)d_in[11];
    float* out = (float*)d_out;

    const size_t smA = (size_t)39984 * sizeof(float);  // 159936 B
    const size_t smB = (size_t)47232 * sizeof(float);  // 188928 B
    cudaFuncSetAttribute(vitA, cudaFuncAttributeMaxDynamicSharedMemorySize, (int)smA);
    cudaFuncSetAttribute(vitB, cudaFuncAttributeMaxDynamicSharedMemorySize, (int)smB);

    vitP<<<(16384 * 784 + 255) / 256, 256>>>(x);
    vitA<<<148, 448, smA>>>(pe, WQ1, WK1, WV1);
    vitB<<<148, 448, smB>>>(WQ2, WK2, WV2, f1w, f1b, f2w, f2b, out);
}

// round 7
// speedup vs baseline: 1.0773x; 1.0773x over previous
#include <cuda_runtime.h>
#include <cstddef>

#define FULLMASK 0xffffffffu

// Global scratch (static __device__ arrays - no allocation at runtime)
static __device__ float g_patch[16384 * 784];      // 51.4 MB patch-major grayscale
static __device__ float g_tok2[16384 * 49 * 16];   // 51.4 MB stage-1 output
static __device__ unsigned g_ctrA;
static __device__ unsigned g_ctrB;

// ---------------------------------------------------------------------------
// Kernel P: grayscale + patch scatter, 4 pixels (one patch row) per thread.
// Also resets the work counters for vitA / vitB (thread 0).
// ---------------------------------------------------------------------------
__global__ void vitP(const float* __restrict__ x)
{
    int t = blockIdx.x * 256 + threadIdx.x;
    if (t == 0) { g_ctrA = 0; g_ctrB = 0; }
    if (t >= 16384 * 196) return;
    int b = t / 196;
    int r = t - b * 196;          // py*7 + sx
    int py = r / 7;
    int sx = r - py * 7;
    const float4* xb = (const float4*)(x + (size_t)b * 2352);
    int off = py * 7 + sx;        // float4 index into 28x28 (196 float4/chan)
    float4 c0 = __ldg(xb + off);
    float4 c1 = __ldg(xb + 196 + off);
    float4 c2 = __ldg(xb + 392 + off);
    float4 g;
    g.x = 0.299f * c0.x + 0.587f * c1.x + 0.114f * c2.x;
    g.y = 0.299f * c0.y + 0.587f * c1.y + 0.114f * c2.y;
    g.z = 0.299f * c0.z + 0.587f * c1.z + 0.114f * c2.z;
    g.w = 0.299f * c0.w + 0.587f * c1.w + 0.114f * c2.w;
    int patch = (py >> 2) * 7 + sx;
    *(float4*)(g_patch + (size_t)b * 784 + patch * 16 + (py & 3) * 4) = g;
}

// 16 FMAs of a float4-quad weight block against patch quads p0..p3
#define FMA16(acc0, acc1, W0, W1, W2, W3)                                   \
    acc0 = fmaf(p0.x, W0.x, acc0); acc1 = fmaf(p0.y, W0.y, acc1);           \
    acc0 = fmaf(p0.z, W0.z, acc0); acc1 = fmaf(p0.w, W0.w, acc1);           \
    acc0 = fmaf(p1.x, W1.x, acc0); acc1 = fmaf(p1.y, W1.y, acc1);           \
    acc0 = fmaf(p1.z, W1.z, acc0); acc1 = fmaf(p1.w, W1.w, acc1);           \
    acc0 = fmaf(p2.x, W2.x, acc0); acc1 = fmaf(p2.y, W2.y, acc1);           \
    acc0 = fmaf(p2.z, W2.z, acc0); acc1 = fmaf(p2.w, W2.w, acc1);           \
    acc0 = fmaf(p3.x, W3.x, acc0); acc1 = fmaf(p3.y, W3.y, acc1);           \
    acc0 = fmaf(p3.z, W3.z, acc0); acc1 = fmaf(p3.w, W3.w, acc1);

// ---------------------------------------------------------------------------
// Kernel A (stage 1): patches -> Q,K -> S gram -> V -> softmax -> tok2
// Warp = 2 half-warps = 2 elements, same s. k/v broadcast through a
// double-buffered 32-float SMEM slot. 768 threads; atomic pair counter.
// SMEM: 3*12544 + 3*784 + 24*64 = 41520 floats = 166080 B.
// ---------------------------------------------------------------------------
__global__ void __launch_bounds__(768, 1) vitA(
    const float* __restrict__ pe,
    const float* __restrict__ WQ1,
    const float* __restrict__ WK1,
    const float* __restrict__ WV1)
{
    extern __shared__ float sm[];
    float* sW = sm;          // 3 * 12544
    float* sB = sm + 37632;  // 3 * 784
    float* sKV = sm + 39984; // 24 warps * 64

    const int tid = threadIdx.x;
    {
        const float* Wg[3] = {WQ1, WK1, WV1};
        for (int w = 0; w < 3; ++w) {
            const float* G = Wg[w];
            float* dst = sW + w * 12544;
            for (int idx = tid; idx < 12544; idx += 768) {
                int s = idx >> 8, r = idx & 255, i = r >> 4, o = r & 15;
                dst[s * 256 + (i >> 2) * 64 + o * 4 + (i & 3)] = G[(s * 16 + o) * 32 + i];
            }
            float* db = sB + w * 784;
            for (int idx = tid; idx < 784; idx += 768) {
                int s = idx >> 4, o = idx & 15;
                const float* gw = G + (s * 16 + o) * 32 + 16;
                const float* pp = pe + s * 16;
                float acc = 0.f;
#pragma unroll
                for (int j = 0; j < 16; ++j) acc = fmaf(pp[j], gw[j], acc);
                db[idx] = acc;
            }
        }
    }
    __syncthreads();

    const int warpId = tid >> 5;
    const int lane = tid & 31;
    const int hh = lane >> 4;
    const int l16 = lane & 15;
    float* kb = sKV + warpId * 64;   // [buf 0/1][lane]

    for (;;) {
        unsigned p;
        if (lane == 0) p = atomicAdd(&g_ctrA, 1u);
        p = __shfl_sync(FULLMASK, p, 0);
        if (p >= 8192) break;
        const int elem = (int)p * 2 + hh;
        const float* pb = g_patch + (size_t)elem * 784;

        float S[16];
#pragma unroll
        for (int e = 0; e < 16; ++e) S[e] = 0.f;

        int cur = 0;
        // ---- pass 1: q,k -> gram ----
#pragma unroll 1
        for (int s = 0; s < 49; ++s) {
            const float4* pv = (const float4*)(pb + s * 16);
            float4 p0 = __ldg(pv + 0), p1 = __ldg(pv + 1);
            float4 p2 = __ldg(pv + 2), p3 = __ldg(pv + 3);

            const float4* wq4 = (const float4*)(sW + s * 256 + l16 * 4);
            float4 a0 = wq4[0], a1 = wq4[16], a2 = wq4[32], a3 = wq4[48];
            float q0 = sB[s * 16 + l16], q1 = 0.f;
            FMA16(q0, q1, a0, a1, a2, a3);

            const float4* wk4 = (const float4*)(sW + 12544 + s * 256 + l16 * 4);
            float4 b0 = wk4[0], b1 = wk4[16], b2 = wk4[32], b3 = wk4[48];
            float k0 = sB[784 + s * 16 + l16], k1 = 0.f;
            FMA16(k0, k1, b0, b1, b2, b3);

            float q = q0 + q1;
            kb[cur * 32 + lane] = k0 + k1;
            __syncwarp();
            const float4* kv4 = (const float4*)(kb + cur * 32 + hh * 16);
            float4 v0 = kv4[0], v1 = kv4[1], v2 = kv4[2], v3 = kv4[3];
            S[0] = fmaf(q, v0.x, S[0]);  S[1] = fmaf(q, v0.y, S[1]);
            S[2] = fmaf(q, v0.z, S[2]);  S[3] = fmaf(q, v0.w, S[3]);
            S[4] = fmaf(q, v1.x, S[4]);  S[5] = fmaf(q, v1.y, S[5]);
            S[6] = fmaf(q, v1.z, S[6]);  S[7] = fmaf(q, v1.w, S[7]);
            S[8] = fmaf(q, v2.x, S[8]);  S[9] = fmaf(q, v2.y, S[9]);
            S[10] = fmaf(q, v2.z, S[10]); S[11] = fmaf(q, v2.w, S[11]);
            S[12] = fmaf(q, v3.x, S[12]); S[13] = fmaf(q, v3.y, S[13]);
            S[14] = fmaf(q, v3.z, S[14]); S[15] = fmaf(q, v3.w, S[15]);
            cur ^= 1;
        }
#pragma unroll
        for (int e = 0; e < 16; ++e) S[e] *= (1.f / 7.f);

        // ---- pass 2: v -> apply S -> softmax(16) -> tok2 ----
        float* ob = g_tok2 + (size_t)elem * 784;
#pragma unroll 1
        for (int s = 0; s < 49; ++s) {
            const float4* pv = (const float4*)(pb + s * 16);
            float4 p0 = __ldg(pv + 0), p1 = __ldg(pv + 1);
            float4 p2 = __ldg(pv + 2), p3 = __ldg(pv + 3);

            const float4* wv4 = (const float4*)(sW + 25088 + s * 256 + l16 * 4);
            float4 a0 = wv4[0], a1 = wv4[16], a2 = wv4[32], a3 = wv4[48];
            float w0 = sB[1568 + s * 16 + l16], w1 = 0.f;
            FMA16(w0, w1, a0, a1, a2, a3);

            kb[cur * 32 + lane] = w0 + w1;
            __syncwarp();
            const float4* vv4 = (const float4*)(kb + cur * 32 + hh * 16);
            float4 v0 = vv4[0], v1 = vv4[1], v2 = vv4[2], v3 = vv4[3];
            float o = 0.f;
            o = fmaf(S[0], v0.x, o);  o = fmaf(S[1], v0.y, o);
            o = fmaf(S[2], v0.z, o);  o = fmaf(S[3], v0.w, o);
            o = fmaf(S[4], v1.x, o);  o = fmaf(S[5], v1.y, o);
            o = fmaf(S[6], v1.z, o);  o = fmaf(S[7], v1.w, o);
            o = fmaf(S[8], v2.x, o);  o = fmaf(S[9], v2.y, o);
            o = fmaf(S[10], v2.z, o); o = fmaf(S[11], v2.w, o);
            o = fmaf(S[12], v3.x, o); o = fmaf(S[13], v3.y, o);
            o = fmaf(S[14], v3.z, o); o = fmaf(S[15], v3.w, o);
            cur ^= 1;

            float m = o;
#pragma unroll
            for (int dd = 8; dd; dd >>= 1)
                m = fmaxf(m, __shfl_xor_sync(FULLMASK, m, dd, 16));
            float ex = __expf(o - m);
            float sum = ex;
#pragma unroll
            for (int dd = 8; dd; dd >>= 1)
                sum += __shfl_xor_sync(FULLMASK, sum, dd, 16);
            ob[s * 16 + l16] = __fdividef(ex, sum);
        }
    }
}

// ---------------------------------------------------------------------------
// Kernel B: tok2 -> QKV2 -> attn(8) -> softmax -> [fc1 fused per-s] -> relu
// -> fc2 -> out.  Warp = 4 octets = 4 elements sharing s. No tok3 storage:
// each s's tok3 value feeds fc1 accumulators h[16] immediately (weights
// transposed [d8][s][j]). Octet split-butterfly reduces h. 640 threads.
// SMEM: 18816 + 6272 + 160 + 16 + 16 + 20*64(kv) + 20*64(hb)
//     = 27840 floats = 111360 B.
// ---------------------------------------------------------------------------
__global__ void __launch_bounds__(640, 1) vitB(
    const float* __restrict__ WQ2,
    const float* __restrict__ WK2,
    const float* __restrict__ WV2,
    const float* __restrict__ f1w,
    const float* __restrict__ f1b,
    const float* __restrict__ f2w,
    const float* __restrict__ f2b,
    float* __restrict__ out)
{
    extern __shared__ float sm[];
    float* sW2 = sm;            // 3 * 6272
    float* sF1t = sm + 18816;   // 6272 : [d8][s][j]
    float* sF2 = sm + 25088;    // 160
    float* sB1 = sm + 25248;    // 16
    float* sB2 = sm + 25264;    // 16
    float* sKV = sm + 25280;    // 20 * 64
    float* sHB = sm + 26560;    // 20 * 64

    const int tid = threadIdx.x;
    {
        const float* Wg[3] = {WQ2, WK2, WV2};
        for (int w = 0; w < 3; ++w) {
            const float* G = Wg[w];
            float* dst = sW2 + w * 6272;
            for (int idx = tid; idx < 6272; idx += 640) {
                int s = idx >> 7, r = idx & 127, i = r >> 3, d = r & 7;
                dst[s * 128 + (i >> 2) * 32 + d * 4 + (i & 3)] = G[(s * 8 + d) * 16 + i];
            }
        }
        for (int idx = tid; idx < 6272; idx += 640) {
            int d = idx / 784, r = idx - d * 784, s = r >> 4, j = r & 15;
            sF1t[(d * 49 + s) * 16 + j] = f1w[j * 392 + s * 8 + d];
        }
        for (int idx = tid; idx < 160; idx += 640) {
            int j = idx / 10, c = idx - j * 10;
            sF2[idx] = f2w[c * 16 + j];
        }
        if (tid < 16) sB1[tid] = f1b[tid];
        if (tid < 10) sB2[tid] = f2b[tid];
    }
    __syncthreads();

    const int warpId = tid >> 5;
    const int lane = tid & 31;
    const int oct = lane >> 3;   // element within group
    const int d8 = lane & 7;     // output dim
    float* kb = sKV + warpId * 64;
    float* hb = sHB + warpId * 64;

    for (;;) {
        unsigned grp;
        if (lane == 0) grp = atomicAdd(&g_ctrB, 1u);
        grp = __shfl_sync(FULLMASK, grp, 0);
        if (grp >= 4096) break;
        const int elem = (int)grp * 4 + oct;
        const float* tb = g_tok2 + (size_t)elem * 784;

        float S2[8];
#pragma unroll
        for (int e = 0; e < 8; ++e) S2[e] = 0.f;

        int cur = 0;
        // ---- pass 1: q2,k2 -> gram ----
#pragma unroll 1
        for (int s = 0; s < 49; ++s) {
            const float4* pv = (const float4*)(tb + s * 16);
            float4 p0 = __ldg(pv + 0), p1 = __ldg(pv + 1);
            float4 p2 = __ldg(pv + 2), p3 = __ldg(pv + 3);

            const float4* wq4 = (const float4*)(sW2 + s * 128 + d8 * 4);
            float4 a0 = wq4[0], a1 = wq4[8], a2 = wq4[16], a3 = wq4[24];
            float q0 = 0.f, q1 = 0.f;
            FMA16(q0, q1, a0, a1, a2, a3);

            const float4* wk4 = (const float4*)(sW2 + 6272 + s * 128 + d8 * 4);
            float4 b0 = wk4[0], b1 = wk4[8], b2 = wk4[16], b3 = wk4[24];
            float k0 = 0.f, k1 = 0.f;
            FMA16(k0, k1, b0, b1, b2, b3);

            float q = q0 + q1;
            kb[cur * 32 + lane] = k0 + k1;
            __syncwarp();
            const float4* kv4 = (const float4*)(kb + cur * 32 + oct * 8);
            float4 v0 = kv4[0], v1 = kv4[1];
            S2[0] = fmaf(q, v0.x, S2[0]); S2[1] = fmaf(q, v0.y, S2[1]);
            S2[2] = fmaf(q, v0.z, S2[2]); S2[3] = fmaf(q, v0.w, S2[3]);
            S2[4] = fmaf(q, v1.x, S2[4]); S2[5] = fmaf(q, v1.y, S2[5]);
            S2[6] = fmaf(q, v1.z, S2[6]); S2[7] = fmaf(q, v1.w, S2[7]);
            cur ^= 1;
        }
#pragma unroll
        for (int e = 0; e < 8; ++e) S2[e] *= (1.f / 7.f);

        // ---- pass 2: v2 -> apply S2 -> softmax(8) -> fc1 fused ----
        float h[16];
#pragma unroll
        for (int j = 0; j < 16; ++j) h[j] = 0.f;

#pragma unroll 1
        for (int s = 0; s < 49; ++s) {
            const float4* pv = (const float4*)(tb + s * 16);
            float4 p0 = __ldg(pv + 0), p1 = __ldg(pv + 1);
            float4 p2 = __ldg(pv + 2), p3 = __ldg(pv + 3);

            const float4* wv4 = (const float4*)(sW2 + 12544 + s * 128 + d8 * 4);
            float4 a0 = wv4[0], a1 = wv4[8], a2 = wv4[16], a3 = wv4[24];
            float w0 = 0.f, w1 = 0.f;
            FMA16(w0, w1, a0, a1, a2, a3);

            kb[cur * 32 + lane] = w0 + w1;
            __syncwarp();
            const float4* vv4 = (const float4*)(kb + cur * 32 + oct * 8);
            float4 v0 = vv4[0], v1 = vv4[1];
            float o = 0.f;
            o = fmaf(S2[0], v0.x, o); o = fmaf(S2[1], v0.y, o);
            o = fmaf(S2[2], v0.z, o); o = fmaf(S2[3], v0.w, o);
            o = fmaf(S2[4], v1.x, o); o = fmaf(S2[5], v1.y, o);
            o = fmaf(S2[6], v1.z, o); o = fmaf(S2[7], v1.w, o);
            cur ^= 1;

            float m = o;
#pragma unroll
            for (int dd = 4; dd; dd >>= 1)
                m = fmaxf(m, __shfl_xor_sync(FULLMASK, m, dd, 8));
            float ex = __expf(o - m);
            float sum = ex;
#pragma unroll
            for (int dd = 4; dd; dd >>= 1)
                sum += __shfl_xor_sync(FULLMASK, sum, dd, 8);
            float tv = __fdividef(ex, sum);   // tok3[s][d8]

            // fc1 fused: h[j] += tok3[s][d8] * W1[j][s*8+d8]
            const float4* wt = (const float4*)(sF1t + (d8 * 49 + s) * 16);
            float4 f0 = wt[0], f1 = wt[1], f2 = wt[2], f3 = wt[3];
            h[0] = fmaf(tv, f0.x, h[0]);  h[1] = fmaf(tv, f0.y, h[1]);
            h[2] = fmaf(tv, f0.z, h[2]);  h[3] = fmaf(tv, f0.w, h[3]);
            h[4] = fmaf(tv, f1.x, h[4]);  h[5] = fmaf(tv, f1.y, h[5]);
            h[6] = fmaf(tv, f1.z, h[6]);  h[7] = fmaf(tv, f1.w, h[7]);
            h[8] = fmaf(tv, f2.x, h[8]);  h[9] = fmaf(tv, f2.y, h[9]);
            h[10] = fmaf(tv, f2.z, h[10]); h[11] = fmaf(tv, f2.w, h[11]);
            h[12] = fmaf(tv, f3.x, h[12]); h[13] = fmaf(tv, f3.y, h[13]);
            h[14] = fmaf(tv, f3.z, h[14]); h[15] = fmaf(tv, f3.w, h[15]);
        }

        // split-butterfly reduce over the 8 octet lanes: 14 shfl total
#pragma unroll
        for (int j = 0; j < 8; ++j) {
            float sendv = (d8 & 1) ? h[j] : h[j + 8];
            float keep  = (d8 & 1) ? h[j + 8] : h[j];
            h[j] = keep + __shfl_xor_sync(FULLMASK, sendv, 1, 8);
        }
#pragma unroll
        for (int j = 0; j < 4; ++j) {
            float sendv = (d8 & 2) ? h[j] : h[j + 4];
            float keep  = (d8 & 2) ? h[j + 4] : h[j];
            h[j] = keep + __shfl_xor_sync(FULLMASK, sendv, 2, 8);
        }
#pragma unroll
        for (int j = 0; j < 2; ++j) {
            float sendv = (d8 & 4) ? h[j] : h[j + 2];
            float keep  = (d8 & 4) ? h[j + 2] : h[j];
            h[j] = keep + __shfl_xor_sync(FULLMASK, sendv, 4, 8);
        }
        int ja = 8 * (d8 & 1) + 4 * ((d8 >> 1) & 1) + 2 * ((d8 >> 2) & 1);
        __syncwarp();
        hb[oct * 16 + ja] = fmaxf(h[0] + sB1[ja], 0.f);
        hb[oct * 16 + ja + 1] = fmaxf(h[1] + sB1[ja + 1], 0.f);
        __syncwarp();

        // ---- fc2 + softmax over 10 (octet-local) ----
        const float* ho = hb + oct * 16;
        int c2 = (d8 < 2) ? (d8 + 8) : 8;
        float lg1 = sB2[d8];
        float lg2 = sB2[c2];
#pragma unroll
        for (int j = 0; j < 16; ++j) {
            float hv = ho[j];
            lg1 = fmaf(hv, sF2[j * 10 + d8], lg1);
            lg2 = fmaf(hv, sF2[j * 10 + c2], lg2);
        }
        float lg2v = (d8 < 2) ? lg2 : -1e30f;
        float m = fmaxf(lg1, lg2v);
#pragma unroll
        for (int dd = 4; dd; dd >>= 1)
            m = fmaxf(m, __shfl_xor_sync(FULLMASK, m, dd, 8));
        float e1 = __expf(lg1 - m);
        float e2 = (d8 < 2) ? __expf(lg2 - m) : 0.f;
        float sum = e1 + e2;
#pragma unroll
        for (int dd = 4; dd; dd >>= 1)
            sum += __shfl_xor_sync(FULLMASK, sum, dd, 8);
        float inv = __fdividef(1.f, sum);
        out[elem * 10 + d8] = e1 * inv;
        if (d8 < 2) out[elem * 10 + 8 + d8] = e2 * inv;
        __syncwarp();  // protect hb before next iteration
    }
}

extern "C" void kernel_launch(void* const* d_in, const int* in_sizes, int n_in,
                              void* d_out, int out_size)
{
    (void)in_sizes; (void)n_in; (void)out_size;
    const float* x   = (const float*)d_in[0];
    const float* pe  = (const float*)d_in[1];
    const float* WQ1 = (const float*)d_in[2];
    const float* WK1 = (const float*)d_in[3];
    const float* WV1 = (const float*)d_in[4];
    const float* WQ2 = (const float*)d_in[5];
    const float* WK2 = (const float*)d_in[6];
    const float* WV2 = (const float*)d_in[7];
    const float* f1w = (const float*)d_in[8];
    const float* f1b = (const float*)d_in[9];
    const float* f2w = (const float*)d_in[10];
    const float* f2b = (const float*)d_in[11];
    float* out = (float*)d_out;

    const size_t smA = (size_t)41520 * sizeof(float);  // 166080 B
    const size_t smB = (size_t)27840 * sizeof(float);  // 111360 B
    cudaFuncSetAttribute(vitA, cudaFuncAttributeMaxDynamicSharedMemorySize, (int)smA);
    cudaFuncSetAttribute(vitB, cudaFuncAttributeMaxDynamicSharedMemorySize, (int)smB);

    vitP<<<(16384 * 196 + 255) / 256, 256>>>(x);
    vitA<<<148, 768, smA>>>(pe, WQ1, WK1, WV1);
    vitB<<<148, 640, smB>>>(WQ2, WK2, WV2, f1w, f1b, f2w, f2b, out);
}

// round 8
// speedup vs baseline: 1.1824x; 1.0976x over previous
#include <cuda_runtime.h>
#include <cstddef>

#define FULLMASK 0xffffffffu

// Global scratch (static __device__ arrays - no allocation at runtime)
static __device__ __align__(16) float g_patch[16384 * 784];   // 51.4 MB
static __device__ __align__(16) float g_tok2[16384 * 784];    // 51.4 MB
static __device__ __align__(16) float g_v[16384 * 784];       // 51.4 MB stage1 V
static __device__ __align__(16) float g_v2[16384 * 392];      // 25.7 MB stage2 V
static __device__ unsigned g_ctrA;
static __device__ unsigned g_ctrB;

// ---------------------------------------------------------------------------
// Kernel P: grayscale + patch scatter, 4 pixels (one patch row) per thread.
// Also resets the work counters for vitA / vitB (thread 0).
// ---------------------------------------------------------------------------
__global__ void vitP(const float* __restrict__ x)
{
    int t = blockIdx.x * 256 + threadIdx.x;
    if (t == 0) { g_ctrA = 0; g_ctrB = 0; }
    if (t >= 16384 * 196) return;
    int b = t / 196;
    int r = t - b * 196;          // py*7 + sx
    int py = r / 7;
    int sx = r - py * 7;
    const float4* xb = (const float4*)(x + (size_t)b * 2352);
    int off = py * 7 + sx;
    float4 c0 = __ldg(xb + off);
    float4 c1 = __ldg(xb + 196 + off);
    float4 c2 = __ldg(xb + 392 + off);
    float4 g;
    g.x = 0.299f * c0.x + 0.587f * c1.x + 0.114f * c2.x;
    g.y = 0.299f * c0.y + 0.587f * c1.y + 0.114f * c2.y;
    g.z = 0.299f * c0.z + 0.587f * c1.z + 0.114f * c2.z;
    g.w = 0.299f * c0.w + 0.587f * c1.w + 0.114f * c2.w;
    int patch = (py >> 2) * 7 + sx;
    *(float4*)(g_patch + (size_t)b * 784 + patch * 16 + (py & 3) * 4) = g;
}

// 16 FMAs of a float4-quad weight block against patch quads p0..p3
#define FMA16(acc0, acc1, W0, W1, W2, W3)                                   \
    acc0 = fmaf(p0.x, W0.x, acc0); acc1 = fmaf(p0.y, W0.y, acc1);           \
    acc0 = fmaf(p0.z, W0.z, acc0); acc1 = fmaf(p0.w, W0.w, acc1);           \
    acc0 = fmaf(p1.x, W1.x, acc0); acc1 = fmaf(p1.y, W1.y, acc1);           \
    acc0 = fmaf(p1.z, W1.z, acc0); acc1 = fmaf(p1.w, W1.w, acc1);           \
    acc0 = fmaf(p2.x, W2.x, acc0); acc1 = fmaf(p2.y, W2.y, acc1);           \
    acc0 = fmaf(p2.z, W2.z, acc0); acc1 = fmaf(p2.w, W2.w, acc1);           \
    acc0 = fmaf(p3.x, W3.x, acc0); acc1 = fmaf(p3.y, W3.y, acc1);           \
    acc0 = fmaf(p3.z, W3.z, acc0); acc1 = fmaf(p3.w, W3.w, acc1);

// ---------------------------------------------------------------------------
// Kernel A (stage 1): single-pass QKV -> gram S (k via SMEM broadcast),
// v stored to g_v. Pass 2: read g_v (prefetched), apply S, softmax -> tok2.
// Warp = 2 half-warps = 2 elements, same s. 640 threads; atomic counter.
// SMEM: 3*12544 + 3*784 + 20*64 = 41264 floats = 165056 B.
// ---------------------------------------------------------------------------
__global__ void __launch_bounds__(640, 1) vitA(
    const float* __restrict__ pe,
    const float* __restrict__ WQ1,
    const float* __restrict__ WK1,
    const float* __restrict__ WV1)
{
    extern __shared__ float sm[];
    float* sW = sm;          // 3 * 12544
    float* sB = sm + 37632;  // 3 * 784
    float* sKV = sm + 39984; // 20 warps * 64

    const int tid = threadIdx.x;
    {
        const float* Wg[3] = {WQ1, WK1, WV1};
        for (int w = 0; w < 3; ++w) {
            const float* G = Wg[w];
            float* dst = sW + w * 12544;
            for (int idx = tid; idx < 12544; idx += 640) {
                int s = idx >> 8, r = idx & 255, i = r >> 4, o = r & 15;
                dst[s * 256 + (i >> 2) * 64 + o * 4 + (i & 3)] = G[(s * 16 + o) * 32 + i];
            }
            float* db = sB + w * 784;
            for (int idx = tid; idx < 784; idx += 640) {
                int s = idx >> 4, o = idx & 15;
                const float* gw = G + (s * 16 + o) * 32 + 16;
                const float* pp = pe + s * 16;
                float acc = 0.f;
#pragma unroll
                for (int j = 0; j < 16; ++j) acc = fmaf(pp[j], gw[j], acc);
                db[idx] = acc;
            }
        }
    }
    __syncthreads();

    const int warpId = tid >> 5;
    const int lane = tid & 31;
    const int hh = lane >> 4;
    const int l16 = lane & 15;
    float* kb = sKV + warpId * 64;   // [buf 0/1][lane]

    for (;;) {
        unsigned p;
        if (lane == 0) p = atomicAdd(&g_ctrA, 1u);
        p = __shfl_sync(FULLMASK, p, 0);
        if (p >= 8192) break;
        const int elem = (int)p * 2 + hh;
        const float* pb = g_patch + (size_t)elem * 784;
        float* vb = g_v + (size_t)elem * 784;

        float S[16];
#pragma unroll
        for (int e = 0; e < 16; ++e) S[e] = 0.f;

        int cur = 0;
        const float4* pv = (const float4*)pb;
        float4 p0 = __ldg(pv + 0), p1 = __ldg(pv + 1);
        float4 p2 = __ldg(pv + 2), p3 = __ldg(pv + 3);

        // ---- pass 1: q,k,v per s; gram S; store v ----
#pragma unroll 1
        for (int s = 0; s < 49; ++s) {
            // prefetch next patch quad
            int sn = (s < 48) ? s + 1 : 48;
            float4 n0 = __ldg(pv + sn * 4 + 0), n1 = __ldg(pv + sn * 4 + 1);
            float4 n2 = __ldg(pv + sn * 4 + 2), n3 = __ldg(pv + sn * 4 + 3);

            const float4* wq4 = (const float4*)(sW + s * 256 + l16 * 4);
            float4 a0 = wq4[0], a1 = wq4[16], a2 = wq4[32], a3 = wq4[48];
            float q0 = sB[s * 16 + l16], q1 = 0.f;
            FMA16(q0, q1, a0, a1, a2, a3);

            const float4* wk4 = (const float4*)(sW + 12544 + s * 256 + l16 * 4);
            float4 b0 = wk4[0], b1 = wk4[16], b2 = wk4[32], b3 = wk4[48];
            float k0 = sB[784 + s * 16 + l16], k1 = 0.f;
            FMA16(k0, k1, b0, b1, b2, b3);

            const float4* wv4 = (const float4*)(sW + 25088 + s * 256 + l16 * 4);
            float4 c0 = wv4[0], c1 = wv4[16], c2 = wv4[32], c3 = wv4[48];
            float w0 = sB[1568 + s * 16 + l16], w1 = 0.f;
            FMA16(w0, w1, c0, c1, c2, c3);

            vb[s * 16 + l16] = w0 + w1;   // store v

            float q = q0 + q1;
            kb[cur * 32 + lane] = k0 + k1;
            __syncwarp();
            const float4* kv4 = (const float4*)(kb + cur * 32 + hh * 16);
            float4 v0 = kv4[0], v1 = kv4[1], v2 = kv4[2], v3 = kv4[3];
            S[0] = fmaf(q, v0.x, S[0]);  S[1] = fmaf(q, v0.y, S[1]);
            S[2] = fmaf(q, v0.z, S[2]);  S[3] = fmaf(q, v0.w, S[3]);
            S[4] = fmaf(q, v1.x, S[4]);  S[5] = fmaf(q, v1.y, S[5]);
            S[6] = fmaf(q, v1.z, S[6]);  S[7] = fmaf(q, v1.w, S[7]);
            S[8] = fmaf(q, v2.x, S[8]);  S[9] = fmaf(q, v2.y, S[9]);
            S[10] = fmaf(q, v2.z, S[10]); S[11] = fmaf(q, v2.w, S[11]);
            S[12] = fmaf(q, v3.x, S[12]); S[13] = fmaf(q, v3.y, S[13]);
            S[14] = fmaf(q, v3.z, S[14]); S[15] = fmaf(q, v3.w, S[15]);
            cur ^= 1;
            p0 = n0; p1 = n1; p2 = n2; p3 = n3;
        }
#pragma unroll
        for (int e = 0; e < 16; ++e) S[e] *= (1.f / 7.f);

        __syncwarp();  // v stores visible to all lanes of the warp

        // ---- pass 2: read v, apply S, softmax(16) -> tok2 (prefetched) ----
        float* ob = g_tok2 + (size_t)elem * 784;
        const float4* vv = (const float4*)vb;
        float4 u0 = vv[0], u1 = vv[1], u2 = vv[2], u3 = vv[3];
#pragma unroll 1
        for (int s = 0; s < 49; ++s) {
            int sn = (s < 48) ? s + 1 : 48;
            float4 n0 = vv[sn * 4 + 0], n1 = vv[sn * 4 + 1];
            float4 n2 = vv[sn * 4 + 2], n3 = vv[sn * 4 + 3];

            float o = 0.f;
            o = fmaf(S[0], u0.x, o);  o = fmaf(S[1], u0.y, o);
            o = fmaf(S[2], u0.z, o);  o = fmaf(S[3], u0.w, o);
            o = fmaf(S[4], u1.x, o);  o = fmaf(S[5], u1.y, o);
            o = fmaf(S[6], u1.z, o);  o = fmaf(S[7], u1.w, o);
            o = fmaf(S[8], u2.x, o);  o = fmaf(S[9], u2.y, o);
            o = fmaf(S[10], u2.z, o); o = fmaf(S[11], u2.w, o);
            o = fmaf(S[12], u3.x, o); o = fmaf(S[13], u3.y, o);
            o = fmaf(S[14], u3.z, o); o = fmaf(S[15], u3.w, o);

            float m = o;
#pragma unroll
            for (int dd = 8; dd; dd >>= 1)
                m = fmaxf(m, __shfl_xor_sync(FULLMASK, m, dd, 16));
            float ex = __expf(o - m);
            float sum = ex;
#pragma unroll
            for (int dd = 8; dd; dd >>= 1)
                sum += __shfl_xor_sync(FULLMASK, sum, dd, 16);
            ob[s * 16 + l16] = __fdividef(ex, sum);
            u0 = n0; u1 = n1; u2 = n2; u3 = n3;
        }
    }
}

// ---------------------------------------------------------------------------
// Kernel B: tok2 -> QKV2 (single pass, v2 -> g_v2) -> attn(8) -> softmax
// -> fc1 fused per-s -> octet butterfly reduce -> relu -> fc2 -> out.
// Warp = 4 octets = 4 elements sharing s. 640 threads; atomic counter.
// SMEM: 18816 + 6272 + 160 + 16 + 16 + 20*64(kv) + 20*64(hb)
//     = 27840 floats = 111360 B.
// ---------------------------------------------------------------------------
__global__ void __launch_bounds__(640, 1) vitB(
    const float* __restrict__ WQ2,
    const float* __restrict__ WK2,
    const float* __restrict__ WV2,
    const float* __restrict__ f1w,
    const float* __restrict__ f1b,
    const float* __restrict__ f2w,
    const float* __restrict__ f2b,
    float* __restrict__ out)
{
    extern __shared__ float sm[];
    float* sW2 = sm;            // 3 * 6272
    float* sF1t = sm + 18816;   // 6272 : [d8][s][j]
    float* sF2 = sm + 25088;    // 160
    float* sB1 = sm + 25248;    // 16
    float* sB2 = sm + 25264;    // 16
    float* sKV = sm + 25280;    // 20 * 64
    float* sHB = sm + 26560;    // 20 * 64

    const int tid = threadIdx.x;
    {
        const float* Wg[3] = {WQ2, WK2, WV2};
        for (int w = 0; w < 3; ++w) {
            const float* G = Wg[w];
            float* dst = sW2 + w * 6272;
            for (int idx = tid; idx < 6272; idx += 640) {
                int s = idx >> 7, r = idx & 127, i = r >> 3, d = r & 7;
                dst[s * 128 + (i >> 2) * 32 + d * 4 + (i & 3)] = G[(s * 8 + d) * 16 + i];
            }
        }
        for (int idx = tid; idx < 6272; idx += 640) {
            int d = idx / 784, r = idx - d * 784, s = r >> 4, j = r & 15;
            sF1t[(d * 49 + s) * 16 + j] = f1w[j * 392 + s * 8 + d];
        }
        for (int idx = tid; idx < 160; idx += 640) {
            int j = idx / 10, c = idx - j * 10;
            sF2[idx] = f2w[c * 16 + j];
        }
        if (tid < 16) sB1[tid] = f1b[tid];
        if (tid < 10) sB2[tid] = f2b[tid];
    }
    __syncthreads();

    const int warpId = tid >> 5;
    const int lane = tid & 31;
    const int oct = lane >> 3;   // element within group
    const int d8 = lane & 7;     // output dim
    float* kb = sKV + warpId * 64;
    float* hb = sHB + warpId * 64;

    for (;;) {
        unsigned grp;
        if (lane == 0) grp = atomicAdd(&g_ctrB, 1u);
        grp = __shfl_sync(FULLMASK, grp, 0);
        if (grp >= 4096) break;
        const int elem = (int)grp * 4 + oct;
        const float* tb = g_tok2 + (size_t)elem * 784;
        float* vb = g_v2 + (size_t)elem * 392;

        float S2[8];
#pragma unroll
        for (int e = 0; e < 8; ++e) S2[e] = 0.f;

        int cur = 0;
        const float4* pv = (const float4*)tb;
        float4 p0 = __ldg(pv + 0), p1 = __ldg(pv + 1);
        float4 p2 = __ldg(pv + 2), p3 = __ldg(pv + 3);

        // ---- pass 1: q2,k2,v2 per s; gram; store v2 ----
#pragma unroll 1
        for (int s = 0; s < 49; ++s) {
            int sn = (s < 48) ? s + 1 : 48;
            float4 n0 = __ldg(pv + sn * 4 + 0), n1 = __ldg(pv + sn * 4 + 1);
            float4 n2 = __ldg(pv + sn * 4 + 2), n3 = __ldg(pv + sn * 4 + 3);

            const float4* wq4 = (const float4*)(sW2 + s * 128 + d8 * 4);
            float4 a0 = wq4[0], a1 = wq4[8], a2 = wq4[16], a3 = wq4[24];
            float q0 = 0.f, q1 = 0.f;
            FMA16(q0, q1, a0, a1, a2, a3);

            const float4* wk4 = (const float4*)(sW2 + 6272 + s * 128 + d8 * 4);
            float4 b0 = wk4[0], b1 = wk4[8], b2 = wk4[16], b3 = wk4[24];
            float k0 = 0.f, k1 = 0.f;
            FMA16(k0, k1, b0, b1, b2, b3);

            const float4* wv4 = (const float4*)(sW2 + 12544 + s * 128 + d8 * 4);
            float4 c0 = wv4[0], c1 = wv4[8], c2 = wv4[16], c3 = wv4[24];
            float w0 = 0.f, w1 = 0.f;
            FMA16(w0, w1, c0, c1, c2, c3);

            vb[s * 8 + d8] = w0 + w1;    // store v2

            float q = q0 + q1;
            kb[cur * 32 + lane] = k0 + k1;
            __syncwarp();
            const float4* kv4 = (const float4*)(kb + cur * 32 + oct * 8);
            float4 v0 = kv4[0], v1 = kv4[1];
            S2[0] = fmaf(q, v0.x, S2[0]); S2[1] = fmaf(q, v0.y, S2[1]);
            S2[2] = fmaf(q, v0.z, S2[2]); S2[3] = fmaf(q, v0.w, S2[3]);
            S2[4] = fmaf(q, v1.x, S2[4]); S2[5] = fmaf(q, v1.y, S2[5]);
            S2[6] = fmaf(q, v1.z, S2[6]); S2[7] = fmaf(q, v1.w, S2[7]);
            cur ^= 1;
            p0 = n0; p1 = n1; p2 = n2; p3 = n3;
        }
#pragma unroll
        for (int e = 0; e < 8; ++e) S2[e] *= (1.f / 7.f);

        __syncwarp();  // v2 stores visible warp-wide

        // ---- pass 2: read v2, apply S2, softmax(8), fc1 fused ----
        float h[16];
#pragma unroll
        for (int j = 0; j < 16; ++j) h[j] = 0.f;

        const float4* vv = (const float4*)vb;
        float4 u0 = vv[0], u1 = vv[1];
#pragma unroll 1
        for (int s = 0; s < 49; ++s) {
            int sn = (s < 48) ? s + 1 : 48;
            float4 n0 = vv[sn * 2 + 0], n1 = vv[sn * 2 + 1];

            float o = 0.f;
            o = fmaf(S2[0], u0.x, o); o = fmaf(S2[1], u0.y, o);
            o = fmaf(S2[2], u0.z, o); o = fmaf(S2[3], u0.w, o);
            o = fmaf(S2[4], u1.x, o); o = fmaf(S2[5], u1.y, o);
            o = fmaf(S2[6], u1.z, o); o = fmaf(S2[7], u1.w, o);

            float m = o;
#pragma unroll
            for (int dd = 4; dd; dd >>= 1)
                m = fmaxf(m, __shfl_xor_sync(FULLMASK, m, dd, 8));
            float ex = __expf(o - m);
            float sum = ex;
#pragma unroll
            for (int dd = 4; dd; dd >>= 1)
                sum += __shfl_xor_sync(FULLMASK, sum, dd, 8);
            float tv = __fdividef(ex, sum);   // tok3[s][d8]

            // fc1 fused: h[j] += tok3[s][d8] * W1[j][s*8+d8]
            const float4* wt = (const float4*)(sF1t + (d8 * 49 + s) * 16);
            float4 f0 = wt[0], f1 = wt[1], f2 = wt[2], f3 = wt[3];
            h[0] = fmaf(tv, f0.x, h[0]);  h[1] = fmaf(tv, f0.y, h[1]);
            h[2] = fmaf(tv, f0.z, h[2]);  h[3] = fmaf(tv, f0.w, h[3]);
            h[4] = fmaf(tv, f1.x, h[4]);  h[5] = fmaf(tv, f1.y, h[5]);
            h[6] = fmaf(tv, f1.z, h[6]);  h[7] = fmaf(tv, f1.w, h[7]);
            h[8] = fmaf(tv, f2.x, h[8]);  h[9] = fmaf(tv, f2.y, h[9]);
            h[10] = fmaf(tv, f2.z, h[10]); h[11] = fmaf(tv, f2.w, h[11]);
            h[12] = fmaf(tv, f3.x, h[12]); h[13] = fmaf(tv, f3.y, h[13]);
            h[14] = fmaf(tv, f3.z, h[14]); h[15] = fmaf(tv, f3.w, h[15]);
            u0 = n0; u1 = n1;
        }

        // split-butterfly reduce over the 8 octet lanes: 14 shfl total
#pragma unroll
        for (int j = 0; j < 8; ++j) {
            float sendv = (d8 & 1) ? h[j] : h[j + 8];
            float keep  = (d8 & 1) ? h[j + 8] : h[j];
            h[j] = keep + __shfl_xor_sync(FULLMASK, sendv, 1, 8);
        }
#pragma unroll
        for (int j = 0; j < 4; ++j) {
            float sendv = (d8 & 2) ? h[j] : h[j + 4];
            float keep  = (d8 & 2) ? h[j + 4] : h[j];
            h[j] = keep + __shfl_xor_sync(FULLMASK, sendv, 2, 8);
        }
#pragma unroll
        for (int j = 0; j < 2; ++j) {
            float sendv = (d8 & 4) ? h[j] : h[j + 2];
            float keep  = (d8 & 4) ? h[j + 2] : h[j];
            h[j] = keep + __shfl_xor_sync(FULLMASK, sendv, 4, 8);
        }
        int ja = 8 * (d8 & 1) + 4 * ((d8 >> 1) & 1) + 2 * ((d8 >> 2) & 1);
        __syncwarp();
        hb[oct * 16 + ja] = fmaxf(h[0] + sB1[ja], 0.f);
        hb[oct * 16 + ja + 1] = fmaxf(h[1] + sB1[ja + 1], 0.f);
        __syncwarp();

        // ---- fc2 + softmax over 10 (octet-local) ----
        const float* ho = hb + oct * 16;
        int c2 = (d8 < 2) ? (d8 + 8) : 8;
        float lg1 = sB2[d8];
        float lg2 = sB2[c2];
#pragma unroll
        for (int j = 0; j < 16; ++j) {
            float hv = ho[j];
            lg1 = fmaf(hv, sF2[j * 10 + d8], lg1);
            lg2 = fmaf(hv, sF2[j * 10 + c2], lg2);
        }
        float lg2v = (d8 < 2) ? lg2 : -1e30f;
        float m = fmaxf(lg1, lg2v);
#pragma unroll
        for (int dd = 4; dd; dd >>= 1)
            m = fmaxf(m, __shfl_xor_sync(FULLMASK, m, dd, 8));
        float e1 = __expf(lg1 - m);
        float e2 = (d8 < 2) ? __expf(lg2 - m) : 0.f;
        float sum = e1 + e2;
#pragma unroll
        for (int dd = 4; dd; dd >>= 1)
            sum += __shfl_xor_sync(FULLMASK, sum, dd, 8);
        float inv = __fdividef(1.f, sum);
        out[elem * 10 + d8] = e1 * inv;
        if (d8 < 2) out[elem * 10 + 8 + d8] = e2 * inv;
        __syncwarp();  // protect hb before next iteration
    }
}

extern "C" void kernel_launch(void* const* d_in, const int* in_sizes, int n_in,
                              void* d_out, int out_size)
{
    (void)in_sizes; (void)n_in; (void)out_size;
    const float* x   = (const float*)d_in[0];
    const float* pe  = (const float*)d_in[1];
    const float* WQ1 = (const float*)d_in[2];
    const float* WK1 = (const float*)d_in[3];
    const float* WV1 = (const float*)d_in[4];
    const float* WQ2 = (const float*)d_in[5];
    const float* WK2 = (const float*)d_in[6];
    const float* WV2 = (const float*)d_in[7];
    const float* f1w = (const float*)d_in[8];
    const float* f1b = (const float*)d_in[9];
    const float* f2w = (const float*)d_in[10];
    const float* f2b = (const float*)d_in[11];
    float* out = (float*)d_out;

    const size_t smA = (size_t)41264 * sizeof(float);  // 165056 B
    const size_t smB = (size_t)27840 * sizeof(float);  // 111360 B
    cudaFuncSetAttribute(vitA, cudaFuncAttributeMaxDynamicSharedMemorySize, (int)smA);
    cudaFuncSetAttribute(vitB, cudaFuncAttributeMaxDynamicSharedMemorySize, (int)smB);

    vitP<<<(16384 * 196 + 255) / 256, 256>>>(x);
    vitA<<<148, 640, smA>>>(pe, WQ1, WK1, WV1);
    vitB<<<148, 640, smB>>>(WQ2, WK2, WV2, f1w, f1b, f2w, f2b, out);
}

// round 9
// speedup vs baseline: 1.1966x; 1.0120x over previous
#include <cuda_runtime.h>
#include <cstddef>

#define FULLMASK 0xffffffffu

// Global scratch (static __device__ arrays - no allocation at runtime)
static __device__ __align__(16) float g_patch[16384 * 784];   // 51.4 MB
static __device__ __align__(16) float g_tok2[16384 * 784];    // 51.4 MB
static __device__ __align__(16) float g_v[16384 * 784];       // 51.4 MB stage1 V
static __device__ __align__(16) float g_v2[16384 * 392];      // 25.7 MB stage2 V
static __device__ unsigned g_ctrA;
static __device__ unsigned g_ctrB;

// ---------------------------------------------------------------------------
// Kernel P: grayscale + patch scatter, 4 pixels (one patch row) per thread.
// Also resets the work counters for vitA / vitB (thread 0).
// ---------------------------------------------------------------------------
__global__ void vitP(const float* __restrict__ x)
{
    int t = blockIdx.x * 256 + threadIdx.x;
    if (t == 0) { g_ctrA = 0; g_ctrB = 0; }
    if (t >= 16384 * 196) return;
    int b = t / 196;
    int r = t - b * 196;          // py*7 + sx
    int py = r / 7;
    int sx = r - py * 7;
    const float4* xb = (const float4*)(x + (size_t)b * 2352);
    int off = py * 7 + sx;
    float4 c0 = __ldg(xb + off);
    float4 c1 = __ldg(xb + 196 + off);
    float4 c2 = __ldg(xb + 392 + off);
    float4 g;
    g.x = 0.299f * c0.x + 0.587f * c1.x + 0.114f * c2.x;
    g.y = 0.299f * c0.y + 0.587f * c1.y + 0.114f * c2.y;
    g.z = 0.299f * c0.z + 0.587f * c1.z + 0.114f * c2.z;
    g.w = 0.299f * c0.w + 0.587f * c1.w + 0.114f * c2.w;
    int patch = (py >> 2) * 7 + sx;
    *(float4*)(g_patch + (size_t)b * 784 + patch * 16 + (py & 3) * 4) = g;
}

// 16 FMAs of a float4-quad weight block against patch quads p0..p3
#define FMA16(acc0, acc1, W0, W1, W2, W3)                                   \
    acc0 = fmaf(p0.x, W0.x, acc0); acc1 = fmaf(p0.y, W0.y, acc1);           \
    acc0 = fmaf(p0.z, W0.z, acc0); acc1 = fmaf(p0.w, W0.w, acc1);           \
    acc0 = fmaf(p1.x, W1.x, acc0); acc1 = fmaf(p1.y, W1.y, acc1);           \
    acc0 = fmaf(p1.z, W1.z, acc0); acc1 = fmaf(p1.w, W1.w, acc1);           \
    acc0 = fmaf(p2.x, W2.x, acc0); acc1 = fmaf(p2.y, W2.y, acc1);           \
    acc0 = fmaf(p2.z, W2.z, acc0); acc1 = fmaf(p2.w, W2.w, acc1);           \
    acc0 = fmaf(p3.x, W3.x, acc0); acc1 = fmaf(p3.y, W3.y, acc1);           \
    acc0 = fmaf(p3.z, W3.z, acc0); acc1 = fmaf(p3.w, W3.w, acc1);

// ---------------------------------------------------------------------------
// Kernel A (stage 1): single-pass QKV (chunks of 7 s-values) -> gram S
// -> v from g_v -> softmax (7-way pipelined shfl) -> tok2.
// Warp = 2 half-warps = 2 elements. 576 threads = 18 warps.
// SMEM: 3*12544 + 3*784 + 18*224 = 44016 floats = 176064 B.
// ---------------------------------------------------------------------------
__global__ void __launch_bounds__(576, 1) vitA(
    const float* __restrict__ pe,
    const float* __restrict__ WQ1,
    const float* __restrict__ WK1,
    const float* __restrict__ WV1)
{
    extern __shared__ float sm[];
    float* sW = sm;          // 3 * 12544
    float* sB = sm + 37632;  // 3 * 784
    float* sKV = sm + 39984; // 18 warps * 224 (7 slots of 32)

    const int tid = threadIdx.x;
    {
        const float* Wg[3] = {WQ1, WK1, WV1};
        for (int w = 0; w < 3; ++w) {
            const float* G = Wg[w];
            float* dst = sW + w * 12544;
            for (int idx = tid; idx < 12544; idx += 576) {
                int s = idx >> 8, r = idx & 255, i = r >> 4, o = r & 15;
                dst[s * 256 + (i >> 2) * 64 + o * 4 + (i & 3)] = G[(s * 16 + o) * 32 + i];
            }
            float* db = sB + w * 784;
            for (int idx = tid; idx < 784; idx += 576) {
                int s = idx >> 4, o = idx & 15;
                const float* gw = G + (s * 16 + o) * 32 + 16;
                const float* pp = pe + s * 16;
                float acc = 0.f;
#pragma unroll
                for (int j = 0; j < 16; ++j) acc = fmaf(pp[j], gw[j], acc);
                db[idx] = acc;
            }
        }
    }
    __syncthreads();

    const int warpId = tid >> 5;
    const int lane = tid & 31;
    const int hh = lane >> 4;
    const int l16 = lane & 15;
    float* kb = sKV + warpId * 224;

    for (;;) {
        unsigned p;
        if (lane == 0) p = atomicAdd(&g_ctrA, 1u);
        p = __shfl_sync(FULLMASK, p, 0);
        if (p >= 8192) break;
        const int elem = (int)p * 2 + hh;
        const float* pb = g_patch + (size_t)elem * 784;
        float* vb = g_v + (size_t)elem * 784;
        const float4* pv = (const float4*)pb;

        float S[16];
#pragma unroll
        for (int e = 0; e < 16; ++e) S[e] = 0.f;

        // ---- pass 1: chunks of 7 s; q,k,v -> gram ----
#pragma unroll 1
        for (int c = 0; c < 7; ++c) {
            float q[7];
#pragma unroll
            for (int t = 0; t < 7; ++t) {
                int s = c * 7 + t;
                const float4* pq = pv + s * 4;
                float4 p0 = __ldg(pq + 0), p1 = __ldg(pq + 1);
                float4 p2 = __ldg(pq + 2), p3 = __ldg(pq + 3);

                const float4* wq4 = (const float4*)(sW + s * 256 + l16 * 4);
                float4 a0 = wq4[0], a1 = wq4[16], a2 = wq4[32], a3 = wq4[48];
                float q0 = sB[s * 16 + l16], q1 = 0.f;
                FMA16(q0, q1, a0, a1, a2, a3);

                const float4* wk4 = (const float4*)(sW + 12544 + s * 256 + l16 * 4);
                float4 b0 = wk4[0], b1 = wk4[16], b2 = wk4[32], b3 = wk4[48];
                float k0 = sB[784 + s * 16 + l16], k1 = 0.f;
                FMA16(k0, k1, b0, b1, b2, b3);

                const float4* wv4 = (const float4*)(sW + 25088 + s * 256 + l16 * 4);
                float4 c0 = wv4[0], c1 = wv4[16], c2 = wv4[32], c3 = wv4[48];
                float w0 = sB[1568 + s * 16 + l16], w1 = 0.f;
                FMA16(w0, w1, c0, c1, c2, c3);

                vb[s * 16 + l16] = w0 + w1;   // store v
                q[t] = q0 + q1;
                kb[t * 32 + lane] = k0 + k1;
            }
            __syncwarp();
#pragma unroll
            for (int t = 0; t < 7; ++t) {
                const float4* kv4 = (const float4*)(kb + t * 32 + hh * 16);
                float4 v0 = kv4[0], v1 = kv4[1], v2 = kv4[2], v3 = kv4[3];
                float qq = q[t];
                S[0] = fmaf(qq, v0.x, S[0]);  S[1] = fmaf(qq, v0.y, S[1]);
                S[2] = fmaf(qq, v0.z, S[2]);  S[3] = fmaf(qq, v0.w, S[3]);
                S[4] = fmaf(qq, v1.x, S[4]);  S[5] = fmaf(qq, v1.y, S[5]);
                S[6] = fmaf(qq, v1.z, S[6]);  S[7] = fmaf(qq, v1.w, S[7]);
                S[8] = fmaf(qq, v2.x, S[8]);  S[9] = fmaf(qq, v2.y, S[9]);
                S[10] = fmaf(qq, v2.z, S[10]); S[11] = fmaf(qq, v2.w, S[11]);
                S[12] = fmaf(qq, v3.x, S[12]); S[13] = fmaf(qq, v3.y, S[13]);
                S[14] = fmaf(qq, v3.z, S[14]); S[15] = fmaf(qq, v3.w, S[15]);
            }
            __syncwarp();
        }
#pragma unroll
        for (int e = 0; e < 16; ++e) S[e] *= (1.f / 7.f);

        // ---- pass 2: chunks of 7; o -> softmax(16) pipelined -> tok2 ----
        float* ob = g_tok2 + (size_t)elem * 784;
        const float4* vv = (const float4*)vb;
#pragma unroll 1
        for (int c = 0; c < 7; ++c) {
            float o[7];
#pragma unroll
            for (int t = 0; t < 7; ++t) {
                const float4* vq = vv + (c * 7 + t) * 4;
                float4 u0 = vq[0], u1 = vq[1], u2 = vq[2], u3 = vq[3];
                float oo = 0.f;
                oo = fmaf(S[0], u0.x, oo);  oo = fmaf(S[1], u0.y, oo);
                oo = fmaf(S[2], u0.z, oo);  oo = fmaf(S[3], u0.w, oo);
                oo = fmaf(S[4], u1.x, oo);  oo = fmaf(S[5], u1.y, oo);
                oo = fmaf(S[6], u1.z, oo);  oo = fmaf(S[7], u1.w, oo);
                oo = fmaf(S[8], u2.x, oo);  oo = fmaf(S[9], u2.y, oo);
                oo = fmaf(S[10], u2.z, oo); oo = fmaf(S[11], u2.w, oo);
                oo = fmaf(S[12], u3.x, oo); oo = fmaf(S[13], u3.y, oo);
                oo = fmaf(S[14], u3.z, oo); oo = fmaf(S[15], u3.w, oo);
                o[t] = oo;
            }
            float mx[7];
#pragma unroll
            for (int t = 0; t < 7; ++t) mx[t] = o[t];
#pragma unroll
            for (int dd = 8; dd; dd >>= 1)
#pragma unroll
                for (int t = 0; t < 7; ++t)
                    mx[t] = fmaxf(mx[t], __shfl_xor_sync(FULLMASK, mx[t], dd, 16));
            float ex[7], su[7];
#pragma unroll
            for (int t = 0; t < 7; ++t) { ex[t] = __expf(o[t] - mx[t]); su[t] = ex[t]; }
#pragma unroll
            for (int dd = 8; dd; dd >>= 1)
#pragma unroll
                for (int t = 0; t < 7; ++t)
                    su[t] += __shfl_xor_sync(FULLMASK, su[t], dd, 16);
#pragma unroll
            for (int t = 0; t < 7; ++t)
                ob[(c * 7 + t) * 16 + l16] = __fdividef(ex[t], su[t]);
        }
    }
}

// ---------------------------------------------------------------------------
// Kernel B: tok2 -> QKV2 (chunks of 7) -> attn(8) -> softmax (pipelined)
// -> fc1 fused -> octet butterfly reduce -> relu -> fc2 -> out.
// Warp = 4 octets = 4 elements. 576 threads = 18 warps.
// SMEM: 18816+6272+160+16+16 + 18*224(kv) + 18*64(hb) = 30464 fl = 121856 B.
// ---------------------------------------------------------------------------
__global__ void __launch_bounds__(576, 1) vitB(
    const float* __restrict__ WQ2,
    const float* __restrict__ WK2,
    const float* __restrict__ WV2,
    const float* __restrict__ f1w,
    const float* __restrict__ f1b,
    const float* __restrict__ f2w,
    const float* __restrict__ f2b,
    float* __restrict__ out)
{
    extern __shared__ float sm[];
    float* sW2 = sm;            // 3 * 6272
    float* sF1t = sm + 18816;   // 6272 : [d8][s][j]
    float* sF2 = sm + 25088;    // 160
    float* sB1 = sm + 25248;    // 16
    float* sB2 = sm + 25264;    // 16
    float* sKV = sm + 25280;    // 18 * 224
    float* sHB = sm + 29312;    // 18 * 64

    const int tid = threadIdx.x;
    {
        const float* Wg[3] = {WQ2, WK2, WV2};
        for (int w = 0; w < 3; ++w) {
            const float* G = Wg[w];
            float* dst = sW2 + w * 6272;
            for (int idx = tid; idx < 6272; idx += 576) {
                int s = idx >> 7, r = idx & 127, i = r >> 3, d = r & 7;
                dst[s * 128 + (i >> 2) * 32 + d * 4 + (i & 3)] = G[(s * 8 + d) * 16 + i];
            }
        }
        for (int idx = tid; idx < 6272; idx += 576) {
            int d = idx / 784, r = idx - d * 784, s = r >> 4, j = r & 15;
            sF1t[(d * 49 + s) * 16 + j] = f1w[j * 392 + s * 8 + d];
        }
        for (int idx = tid; idx < 160; idx += 576) {
            int j = idx / 10, c = idx - j * 10;
            sF2[idx] = f2w[c * 16 + j];
        }
        if (tid < 16) sB1[tid] = f1b[tid];
        if (tid < 10) sB2[tid] = f2b[tid];
    }
    __syncthreads();

    const int warpId = tid >> 5;
    const int lane = tid & 31;
    const int oct = lane >> 3;   // element within group
    const int d8 = lane & 7;     // output dim
    float* kb = sKV + warpId * 224;
    float* hb = sHB + warpId * 64;

    for (;;) {
        unsigned grp;
        if (lane == 0) grp = atomicAdd(&g_ctrB, 1u);
        grp = __shfl_sync(FULLMASK, grp, 0);
        if (grp >= 4096) break;
        const int elem = (int)grp * 4 + oct;
        const float* tb = g_tok2 + (size_t)elem * 784;
        float* vb = g_v2 + (size_t)elem * 392;
        const float4* pv = (const float4*)tb;

        float S2[8];
#pragma unroll
        for (int e = 0; e < 8; ++e) S2[e] = 0.f;

        // ---- pass 1: chunks of 7; q2,k2,v2 -> gram ----
#pragma unroll 1
        for (int c = 0; c < 7; ++c) {
            float q[7];
#pragma unroll
            for (int t = 0; t < 7; ++t) {
                int s = c * 7 + t;
                const float4* pq = pv + s * 4;
                float4 p0 = __ldg(pq + 0), p1 = __ldg(pq + 1);
                float4 p2 = __ldg(pq + 2), p3 = __ldg(pq + 3);

                const float4* wq4 = (const float4*)(sW2 + s * 128 + d8 * 4);
                float4 a0 = wq4[0], a1 = wq4[8], a2 = wq4[16], a3 = wq4[24];
                float q0 = 0.f, q1 = 0.f;
                FMA16(q0, q1, a0, a1, a2, a3);

                const float4* wk4 = (const float4*)(sW2 + 6272 + s * 128 + d8 * 4);
                float4 b0 = wk4[0], b1 = wk4[8], b2 = wk4[16], b3 = wk4[24];
                float k0 = 0.f, k1 = 0.f;
                FMA16(k0, k1, b0, b1, b2, b3);

                const float4* wv4 = (const float4*)(sW2 + 12544 + s * 128 + d8 * 4);
                float4 c0 = wv4[0], c1 = wv4[8], c2 = wv4[16], c3 = wv4[24];
                float w0 = 0.f, w1 = 0.f;
                FMA16(w0, w1, c0, c1, c2, c3);

                vb[s * 8 + d8] = w0 + w1;    // store v2
                q[t] = q0 + q1;
                kb[t * 32 + lane] = k0 + k1;
            }
            __syncwarp();
#pragma unroll
            for (int t = 0; t < 7; ++t) {
                const float4* kv4 = (const float4*)(kb + t * 32 + oct * 8);
                float4 v0 = kv4[0], v1 = kv4[1];
                float qq = q[t];
                S2[0] = fmaf(qq, v0.x, S2[0]); S2[1] = fmaf(qq, v0.y, S2[1]);
                S2[2] = fmaf(qq, v0.z, S2[2]); S2[3] = fmaf(qq, v0.w, S2[3]);
                S2[4] = fmaf(qq, v1.x, S2[4]); S2[5] = fmaf(qq, v1.y, S2[5]);
                S2[6] = fmaf(qq, v1.z, S2[6]); S2[7] = fmaf(qq, v1.w, S2[7]);
            }
            __syncwarp();
        }
#pragma unroll
        for (int e = 0; e < 8; ++e) S2[e] *= (1.f / 7.f);

        // ---- pass 2: chunks of 7; o -> softmax(8) pipelined -> fc1 fused ----
        float h[16];
#pragma unroll
        for (int j = 0; j < 16; ++j) h[j] = 0.f;
        const float4* vv = (const float4*)vb;

#pragma unroll 1
        for (int c = 0; c < 7; ++c) {
            float o[7];
#pragma unroll
            for (int t = 0; t < 7; ++t) {
                const float4* vq = vv + (c * 7 + t) * 2;
                float4 u0 = vq[0], u1 = vq[1];
                float oo = 0.f;
                oo = fmaf(S2[0], u0.x, oo); oo = fmaf(S2[1], u0.y, oo);
                oo = fmaf(S2[2], u0.z, oo); oo = fmaf(S2[3], u0.w, oo);
                oo = fmaf(S2[4], u1.x, oo); oo = fmaf(S2[5], u1.y, oo);
                oo = fmaf(S2[6], u1.z, oo); oo = fmaf(S2[7], u1.w, oo);
                o[t] = oo;
            }
            float mx[7];
#pragma unroll
            for (int t = 0; t < 7; ++t) mx[t] = o[t];
#pragma unroll
            for (int dd = 4; dd; dd >>= 1)
#pragma unroll
                for (int t = 0; t < 7; ++t)
                    mx[t] = fmaxf(mx[t], __shfl_xor_sync(FULLMASK, mx[t], dd, 8));
            float ex[7], su[7];
#pragma unroll
            for (int t = 0; t < 7; ++t) { ex[t] = __expf(o[t] - mx[t]); su[t] = ex[t]; }
#pragma unroll
            for (int dd = 4; dd; dd >>= 1)
#pragma unroll
                for (int t = 0; t < 7; ++t)
                    su[t] += __shfl_xor_sync(FULLMASK, su[t], dd, 8);
#pragma unroll
            for (int t = 0; t < 7; ++t) {
                float tv = __fdividef(ex[t], su[t]);   // tok3[s][d8]
                const float4* wt = (const float4*)(sF1t + (d8 * 49 + c * 7 + t) * 16);
                float4 f0 = wt[0], f1 = wt[1], f2 = wt[2], f3 = wt[3];
                h[0] = fmaf(tv, f0.x, h[0]);  h[1] = fmaf(tv, f0.y, h[1]);
                h[2] = fmaf(tv, f0.z, h[2]);  h[3] = fmaf(tv, f0.w, h[3]);
                h[4] = fmaf(tv, f1.x, h[4]);  h[5] = fmaf(tv, f1.y, h[5]);
                h[6] = fmaf(tv, f1.z, h[6]);  h[7] = fmaf(tv, f1.w, h[7]);
                h[8] = fmaf(tv, f2.x, h[8]);  h[9] = fmaf(tv, f2.y, h[9]);
                h[10] = fmaf(tv, f2.z, h[10]); h[11] = fmaf(tv, f2.w, h[11]);
                h[12] = fmaf(tv, f3.x, h[12]); h[13] = fmaf(tv, f3.y, h[13]);
                h[14] = fmaf(tv, f3.z, h[14]); h[15] = fmaf(tv, f3.w, h[15]);
            }
        }

        // split-butterfly reduce over the 8 octet lanes: 14 shfl total
#pragma unroll
        for (int j = 0; j < 8; ++j) {
            float sendv = (d8 & 1) ? h[j] : h[j + 8];
            float keep  = (d8 & 1) ? h[j + 8] : h[j];
            h[j] = keep + __shfl_xor_sync(FULLMASK, sendv, 1, 8);
        }
#pragma unroll
        for (int j = 0; j < 4; ++j) {
            float sendv = (d8 & 2) ? h[j] : h[j + 4];
            float keep  = (d8 & 2) ? h[j + 4] : h[j];
            h[j] = keep + __shfl_xor_sync(FULLMASK, sendv, 2, 8);
        }
#pragma unroll
        for (int j = 0; j < 2; ++j) {
            float sendv = (d8 & 4) ? h[j] : h[j + 2];
            float keep  = (d8 & 4) ? h[j + 2] : h[j];
            h[j] = keep + __shfl_xor_sync(FULLMASK, sendv, 4, 8);
        }
        int ja = 8 * (d8 & 1) + 4 * ((d8 >> 1) & 1) + 2 * ((d8 >> 2) & 1);
        __syncwarp();
        hb[oct * 16 + ja] = fmaxf(h[0] + sB1[ja], 0.f);
        hb[oct * 16 + ja + 1] = fmaxf(h[1] + sB1[ja + 1], 0.f);
        __syncwarp();

        // ---- fc2 + softmax over 10 (octet-local) ----
        const float* ho = hb + oct * 16;
        int c2 = (d8 < 2) ? (d8 + 8) : 8;
        float lg1 = sB2[d8];
        float lg2 = sB2[c2];
#pragma unroll
        for (int j = 0; j < 16; ++j) {
            float hv = ho[j];
            lg1 = fmaf(hv, sF2[j * 10 + d8], lg1);
            lg2 = fmaf(hv, sF2[j * 10 + c2], lg2);
        }
        float lg2v = (d8 < 2) ? lg2 : -1e30f;
        float m = fmaxf(lg1, lg2v);
#pragma unroll
        for (int dd = 4; dd; dd >>= 1)
            m = fmaxf(m, __shfl_xor_sync(FULLMASK, m, dd, 8));
        float e1 = __expf(lg1 - m);
        float e2 = (d8 < 2) ? __expf(lg2 - m) : 0.f;
        float sum = e1 + e2;
#pragma unroll
        for (int dd = 4; dd; dd >>= 1)
            sum += __shfl_xor_sync(FULLMASK, sum, dd, 8);
        float inv = __fdividef(1.f, sum);
        out[elem * 10 + d8] = e1 * inv;
        if (d8 < 2) out[elem * 10 + 8 + d8] = e2 * inv;
        __syncwarp();  // protect hb before next iteration
    }
}

extern "C" void kernel_launch(void* const* d_in, const int* in_sizes, int n_in,
                              void* d_out, int out_size)
{
    (void)in_sizes; (void)n_in; (void)out_size;
    const float* x   = (const float*)d_in[0];
    const float* pe  = (const float*)d_in[1];
    const float* WQ1 = (const float*)d_in[2];
    const float* WK1 = (const float*)d_in[3];
    const float* WV1 = (const float*)d_in[4];
    const float* WQ2 = (const float*)d_in[5];
    const float* WK2 = (const float*)d_in[6];
    const float* WV2 = (const float*)d_in[7];
    const float* f1w = (const float*)d_in[8];
    const float* f1b = (const float*)d_in[9];
    const float* f2w = (const float*)d_in[10];
    const float* f2b = (const float*)d_in[11];
    float* out = (float*)d_out;

    const size_t smA = (size_t)44016 * sizeof(float);  // 176064 B
    const size_t smB = (size_t)30464 * sizeof(float);  // 121856 B
    cudaFuncSetAttribute(vitA, cudaFuncAttributeMaxDynamicSharedMemorySize, (int)smA);
    cudaFuncSetAttribute(vitB, cudaFuncAttributeMaxDynamicSharedMemorySize, (int)smB);

    vitP<<<(16384 * 196 + 255) / 256, 256>>>(x);
    vitA<<<148, 576, smA>>>(pe, WQ1, WK1, WV1);
    vitB<<<148, 576, smB>>>(WQ2, WK2, WV2, f1w, f1b, f2w, f2b, out);
}